// round 10
// baseline (speedup 1.0000x reference)
#include <cuda_runtime.h>
#include <cuda_fp16.h>
#include <stdint.h>

#define BB   512
#define TW   512
#define TCC  512
#define INP  16
#define HID  64
#define FD   8
#define SPB  4
#define NT   512
#define HPAD 68
#define U0S  88     // uf0 stride in halfs (K=80 + pad)
#define U1S  136    // uf1 stride in halfs (K=128 + pad)

__device__ __forceinline__ float tanha(float x) {
    float r; asm("tanh.approx.f32 %0, %1;" : "=f"(r) : "f"(x)); return r;
}
__device__ __forceinline__ float sigf(float x) {
    return fmaf(tanha(0.5f * x), 0.5f, 0.5f);
}
__device__ __forceinline__ uint32_t h2(float a, float b) {
    __half2 h = __floats2half2_rn(a, b);
    return *reinterpret_cast<uint32_t*>(&h);
}
__device__ __forceinline__ void mma16816(
    float &d0, float &d1, float &d2, float &d3,
    uint32_t a0, uint32_t a1, uint32_t a2, uint32_t a3,
    uint32_t b0, uint32_t b1)
{
    asm("mma.sync.aligned.m16n8k16.row.col.f32.f16.f16.f32 "
        "{%0,%1,%2,%3},{%4,%5,%6,%7},{%8,%9},{%0,%1,%2,%3};"
        : "+f"(d0), "+f"(d1), "+f"(d2), "+f"(d3)
        : "r"(a0), "r"(a1), "r"(a2), "r"(a3), "r"(b0), "r"(b1));
}
__device__ __forceinline__ float sx16(float v) {
    return __shfl_xor_sync(0xFFFFFFFFu, v, 16);
}

__global__ __launch_bounds__(NT, 1) void lstm_ar_kernel(
    const float* __restrict__ x,     const int* __restrict__ lenx_g,
    const float* __restrict__ ctx,   const int* __restrict__ lctx_g,
    const float* __restrict__ Wih0,  const float* __restrict__ Whh0,
    const float* __restrict__ bih0,  const float* __restrict__ bhh0,
    const float* __restrict__ Wih1,  const float* __restrict__ Whh1,
    const float* __restrict__ bih1,  const float* __restrict__ bhh1,
    const float* __restrict__ Wd,    const float* __restrict__ bd,
    float* __restrict__ out)
{
    // B operands, n-major: uf0[n][k] = [x(16) | h0(64)] (K=80), uf1 = [h0 | h1] (K=128)
    __shared__ __align__(16) __half uf0[8][U0S];
    __shared__ __align__(16) __half uf1[8][U1S];
    __shared__ __align__(16) float h1sh[SPB][HPAD];
    __shared__ float wdsh[FD * 65];
    __shared__ float bdsh[FD];
    __shared__ float elem[SPB][FD];
    __shared__ int   lens[SPB];
    __shared__ int   ldec[SPB];

    const int tid = threadIdx.x;
    const int s0  = blockIdx.x * SPB;

    // ---- fill invalid output rows with -999 ----
    {
        const float4 m = make_float4(-999.f, -999.f, -999.f, -999.f);
        #pragma unroll
        for (int s = 0; s < SPB; s++) {
            int lc = lctx_g[s0 + s];
            float4* po = (float4*)(out + (size_t)(s0 + s) * TCC * FD);
            for (int i = lc * 2 + tid; i < (TCC * FD) / 4; i += NT) po[i] = m;
        }
    }

    // ---- zero B buffers ----
    {
        __half z = __float2half(0.f);
        __half* p0 = &uf0[0][0];
        for (int i = tid; i < 8 * U0S; i += NT) p0[i] = z;
        __half* p1 = &uf1[0][0];
        for (int i = tid; i < 8 * U1S; i += NT) p1[i] = z;
    }

    // ---- permuted-row mma identities ----
    // warp w M-tile: local row l = 4*gate + uu -> weight row 64*gate + (4w+uu)
    const int w    = tid >> 5, lane = tid & 31;
    const int g    = lane >> 2, q = lane & 3;
    const int c0   = 2 * q;
    const int uu   = g & 3;
    const int un   = 4 * w + uu;            // unit index 0..63
    const int gi0  = g >> 2;                // 0 or 1
    const int rA   = 64 * gi0 + un;         // frag rows d0,d1 (gate i or f)
    const int rB   = rA + 128;              // frag rows d2,d3 (gate g or o)
    const bool low = (g < 4);               // low: (i, g-gate) -> layer0 combine
                                            // high: (f, o)     -> layer1 combine

    // A fragments (fp16 weights, permuted rows)
    uint32_t f0[5][4];   // g0 GEMM: [Wih0 | Whh0], K = 80
    uint32_t f1[8][4];   // g1 GEMM: [Wih1 | Whh1], K = 128
    {
        f0[0][0] = h2(Wih0[rA * INP + c0],     Wih0[rA * INP + c0 + 1]);
        f0[0][1] = h2(Wih0[rB * INP + c0],     Wih0[rB * INP + c0 + 1]);
        f0[0][2] = h2(Wih0[rA * INP + c0 + 8], Wih0[rA * INP + c0 + 9]);
        f0[0][3] = h2(Wih0[rB * INP + c0 + 8], Wih0[rB * INP + c0 + 9]);
        #pragma unroll
        for (int kt = 1; kt < 5; kt++) {
            int kb = (kt - 1) * 16;
            f0[kt][0] = h2(Whh0[rA * HID + kb + c0],     Whh0[rA * HID + kb + c0 + 1]);
            f0[kt][1] = h2(Whh0[rB * HID + kb + c0],     Whh0[rB * HID + kb + c0 + 1]);
            f0[kt][2] = h2(Whh0[rA * HID + kb + c0 + 8], Whh0[rA * HID + kb + c0 + 9]);
            f0[kt][3] = h2(Whh0[rB * HID + kb + c0 + 8], Whh0[rB * HID + kb + c0 + 9]);
        }
        #pragma unroll
        for (int kt = 0; kt < 4; kt++) {
            int kb = kt * 16;
            f1[kt][0] = h2(Wih1[rA * HID + kb + c0],     Wih1[rA * HID + kb + c0 + 1]);
            f1[kt][1] = h2(Wih1[rB * HID + kb + c0],     Wih1[rB * HID + kb + c0 + 1]);
            f1[kt][2] = h2(Wih1[rA * HID + kb + c0 + 8], Wih1[rA * HID + kb + c0 + 9]);
            f1[kt][3] = h2(Wih1[rB * HID + kb + c0 + 8], Wih1[rB * HID + kb + c0 + 9]);
        }
        #pragma unroll
        for (int kt = 4; kt < 8; kt++) {
            int kb = (kt - 4) * 16;
            f1[kt][0] = h2(Whh1[rA * HID + kb + c0],     Whh1[rA * HID + kb + c0 + 1]);
            f1[kt][1] = h2(Whh1[rB * HID + kb + c0],     Whh1[rB * HID + kb + c0 + 1]);
            f1[kt][2] = h2(Whh1[rA * HID + kb + c0 + 8], Whh1[rA * HID + kb + c0 + 9]);
            f1[kt][3] = h2(Whh1[rB * HID + kb + c0 + 8], Whh1[rB * HID + kb + c0 + 9]);
        }
    }
    const float b0a = bih0[rA] + bhh0[rA], b0b = bih0[rB] + bhh0[rB];
    const float b1a = bih1[rA] + bhh1[rA], b1b = bih1[rB] + bhh1[rB];

    if (tid < SPB) { lens[tid] = lenx_g[s0 + tid]; ldec[tid] = lctx_g[s0 + tid] - 1; }
    for (int i = tid; i < FD * HID; i += NT) wdsh[(i >> 6) * 65 + (i & 63)] = Wd[i];
    if (tid < FD) bdsh[tid] = bd[tid];
    if (tid < NT / 2) {  // init h1sh via first 256 threads (4*64 slots)
        h1sh[(tid >> 6)][tid & 63] = 0.f;
    }

    __syncthreads();

    const int Tenc = max(max(lens[0], lens[1]), max(lens[2], lens[3]));
    const int Tdec = max(max(ldec[0], ldec[1]), max(ldec[2], ldec[3]));
    int le0 = 0, le1 = 0, ld0 = 0, ld1 = 0;
    if (q < 2) { le0 = lens[c0]; le1 = lens[c0 + 1]; ld0 = ldec[c0]; ld1 = ldec[c0 + 1]; }

    const int ps = tid >> 4, pk = tid & 15;  // x prefetch (tid < 64)
    const int ds = tid >> 3, dk = tid & 7;   // ctx prefetch / projection (tid < 32)

    float D0[4], D1[4];     // gate fragments: D0 = g0(t), D1 = g1(t-1)
    float cs0 = 0.f, cs1 = 0.f;   // cell states for cols c0, c0+1 (layer = low?0:1)

    // ---- encoder prologue: x(0) -> uf0; D0 = g0(0) (h0 = 0) ----
    if (tid < 64) uf0[ps][pk] = __float2half(x[((size_t)(s0 + ps) * TW) * INP + pk]);
    __syncthreads();
    {
        float u0 = b0a, u1 = b0a, u2 = b0b, u3 = b0b;
        #pragma unroll
        for (int kt = 0; kt < 5; kt++) {
            uint32_t bv0 = *reinterpret_cast<const uint32_t*>(&uf0[g][kt * 16 + c0]);
            uint32_t bv1 = *reinterpret_cast<const uint32_t*>(&uf0[g][kt * 16 + c0 + 8]);
            mma16816(u0, u1, u2, u3, f0[kt][0], f0[kt][1], f0[kt][2], f0[kt][3], bv0, bv1);
        }
        D0[0] = u0; D0[1] = u1; D0[2] = u2; D0[3] = u3;
        D1[0] = D1[1] = D1[2] = D1[3] = 0.f;
    }
    float xn = 0.f;
    if (tid < 64) xn = x[((size_t)(s0 + ps) * TW + min(1, TW - 1)) * INP + pk];
    __syncthreads();

    // ===================== encoder =====================
    for (int t = 0; t < Tenc; t++) {
        // ---- phase A: register combine + h STS + x rotate ----
        if (tid < 64) {
            uf0[ps][pk] = __float2half(xn);
            int tt = (t + 2 < TW) ? t + 2 : TW - 1;
            xn = x[((size_t)(s0 + ps) * TW + tt) * INP + pk];
        }
        {
            float r00 = sx16(D0[0]), r01 = sx16(D0[1]), r02 = sx16(D0[2]), r03 = sx16(D0[3]);
            float r10 = sx16(D1[0]), r11 = sx16(D1[1]), r12 = sx16(D1[2]), r13 = sx16(D1[3]);
            if (q < 2) {
                if (low) {   // layer-0 combine at step t: own (i,g), recv (f,o)
                    if (t < le0) {
                        float fi = sigf(D0[0]), ff = sigf(r00), fg = tanha(D0[2]), fo = sigf(r02);
                        cs0 = ff * cs0 + fi * fg;
                        __half hf = __float2half(fo * tanha(cs0));
                        uf0[c0][16 + un] = hf; uf1[c0][un] = hf;
                    }
                    if (t < le1) {
                        float fi = sigf(D0[1]), ff = sigf(r01), fg = tanha(D0[3]), fo = sigf(r03);
                        cs1 = ff * cs1 + fi * fg;
                        __half hf = __float2half(fo * tanha(cs1));
                        uf0[c0 + 1][16 + un] = hf; uf1[c0 + 1][un] = hf;
                    }
                } else if (t > 0) {   // layer-1 combine at step t-1: own (f,o), recv (i,g)
                    if (t - 1 < le0) {
                        float fi = sigf(r10), ff = sigf(D1[0]), fg = tanha(r12), fo = sigf(D1[2]);
                        cs0 = ff * cs0 + fi * fg;
                        float h = fo * tanha(cs0);
                        uf1[c0][64 + un] = __float2half(h); h1sh[c0][un] = h;
                    }
                    if (t - 1 < le1) {
                        float fi = sigf(r11), ff = sigf(D1[1]), fg = tanha(r13), fo = sigf(D1[3]);
                        cs1 = ff * cs1 + fi * fg;
                        float h = fo * tanha(cs1);
                        uf1[c0 + 1][64 + un] = __float2half(h); h1sh[c0 + 1][un] = h;
                    }
                }
            }
        }
        __syncthreads();

        // ---- phase B: GEMMs (split accumulation chains) ----
        {
            float p0 = b1a, p1 = b1a, p2 = b1b, p3 = b1b;
            float s0v = 0.f, s1v = 0.f, s2v = 0.f, s3v = 0.f;
            #pragma unroll
            for (int kt = 0; kt < 4; kt++) {
                uint32_t bv0 = *reinterpret_cast<const uint32_t*>(&uf1[g][kt * 16 + c0]);
                uint32_t bv1 = *reinterpret_cast<const uint32_t*>(&uf1[g][kt * 16 + c0 + 8]);
                mma16816(p0, p1, p2, p3, f1[kt][0], f1[kt][1], f1[kt][2], f1[kt][3], bv0, bv1);
            }
            #pragma unroll
            for (int kt = 4; kt < 8; kt++) {
                uint32_t bv0 = *reinterpret_cast<const uint32_t*>(&uf1[g][kt * 16 + c0]);
                uint32_t bv1 = *reinterpret_cast<const uint32_t*>(&uf1[g][kt * 16 + c0 + 8]);
                mma16816(s0v, s1v, s2v, s3v, f1[kt][0], f1[kt][1], f1[kt][2], f1[kt][3], bv0, bv1);
            }
            D1[0] = p0 + s0v; D1[1] = p1 + s1v; D1[2] = p2 + s2v; D1[3] = p3 + s3v;

            float u0 = b0a, u1 = b0a, u2 = b0b, u3 = b0b;
            float v0 = 0.f, v1 = 0.f, v2 = 0.f, v3 = 0.f;
            #pragma unroll
            for (int kt = 0; kt < 3; kt++) {
                uint32_t bv0 = *reinterpret_cast<const uint32_t*>(&uf0[g][kt * 16 + c0]);
                uint32_t bv1 = *reinterpret_cast<const uint32_t*>(&uf0[g][kt * 16 + c0 + 8]);
                mma16816(u0, u1, u2, u3, f0[kt][0], f0[kt][1], f0[kt][2], f0[kt][3], bv0, bv1);
            }
            #pragma unroll
            for (int kt = 3; kt < 5; kt++) {
                uint32_t bv0 = *reinterpret_cast<const uint32_t*>(&uf0[g][kt * 16 + c0]);
                uint32_t bv1 = *reinterpret_cast<const uint32_t*>(&uf0[g][kt * 16 + c0 + 8]);
                mma16816(v0, v1, v2, v3, f0[kt][0], f0[kt][1], f0[kt][2], f0[kt][3], bv0, bv1);
            }
            D0[0] = u0 + v0; D0[1] = u1 + v1; D0[2] = u2 + v2; D0[3] = u3 + v3;
        }
        __syncthreads();
    }

    // ---- encoder epilogue: combine1(Tenc-1) ----
    {
        float r10 = sx16(D1[0]), r11 = sx16(D1[1]), r12 = sx16(D1[2]), r13 = sx16(D1[3]);
        if (q < 2 && !low) {
            if (Tenc - 1 < le0) {
                float fi = sigf(r10), ff = sigf(D1[0]), fg = tanha(r12), fo = sigf(D1[2]);
                cs0 = ff * cs0 + fi * fg;
                float h = fo * tanha(cs0);
                uf1[c0][64 + un] = __float2half(h); h1sh[c0][un] = h;
            }
            if (Tenc - 1 < le1) {
                float fi = sigf(r11), ff = sigf(D1[1]), fg = tanha(r13), fo = sigf(D1[3]);
                cs1 = ff * cs1 + fi * fg;
                float h = fo * tanha(cs1);
                uf1[c0 + 1][64 + un] = __float2half(h); h1sh[c0 + 1][un] = h;
            }
        }
    }
    __syncthreads();

    // ===================== element = h1 @ Wd.T + bd =====================
    if (tid < 32) {
        float a0 = bdsh[dk], a1 = 0.f, a2 = 0.f, a3 = 0.f;
        #pragma unroll
        for (int j = 0; j < HID; j += 4) {
            a0 = fmaf(wdsh[dk * 65 + j    ], h1sh[ds][j    ], a0);
            a1 = fmaf(wdsh[dk * 65 + j + 1], h1sh[ds][j + 1], a1);
            a2 = fmaf(wdsh[dk * 65 + j + 2], h1sh[ds][j + 2], a2);
            a3 = fmaf(wdsh[dk * 65 + j + 3], h1sh[ds][j + 3], a3);
        }
        float e = (a0 + a1) + (a2 + a3);
        elem[ds][dk] = e;
        out[(size_t)(s0 + ds) * TCC * FD + dk] = e;
    }
    __syncthreads();

    // ---- decoder prologue: dec input = [elem | ctx(0)]; D0 = g0_dec(0) ----
    if (tid < 64 && pk < 8) uf0[ps][pk] = __float2half(elem[ps][pk]);
    if (tid < 32) uf0[ds][8 + dk] = __float2half(ctx[((size_t)(s0 + ds) * TCC) * FD + dk]);
    __syncthreads();
    {
        float u0 = b0a, u1 = b0a, u2 = b0b, u3 = b0b;
        #pragma unroll
        for (int kt = 0; kt < 5; kt++) {
            uint32_t bv0 = *reinterpret_cast<const uint32_t*>(&uf0[g][kt * 16 + c0]);
            uint32_t bv1 = *reinterpret_cast<const uint32_t*>(&uf0[g][kt * 16 + c0 + 8]);
            mma16816(u0, u1, u2, u3, f0[kt][0], f0[kt][1], f0[kt][2], f0[kt][3], bv0, bv1);
        }
        D0[0] = u0; D0[1] = u1; D0[2] = u2; D0[3] = u3;
    }
    float cn = 0.f;
    if (tid < 32) cn = ctx[((size_t)(s0 + ds) * TCC + min(1, TCC - 1)) * FD + dk];
    __syncthreads();

    // ===================== decoder =====================
    for (int t = 0; t < Tdec; t++) {
        // ---- phase A: register combine + h STS + ctx rotate ----
        if (tid < 32) {
            uf0[ds][8 + dk] = __float2half(cn);
            int tt = (t + 2 < TCC) ? t + 2 : TCC - 1;
            cn = ctx[((size_t)(s0 + ds) * TCC + tt) * FD + dk];
        }
        {
            float r00 = sx16(D0[0]), r01 = sx16(D0[1]), r02 = sx16(D0[2]), r03 = sx16(D0[3]);
            float r10 = sx16(D1[0]), r11 = sx16(D1[1]), r12 = sx16(D1[2]), r13 = sx16(D1[3]);
            if (q < 2) {
                if (low) {
                    if (t < ld0) {
                        float fi = sigf(D0[0]), ff = sigf(r00), fg = tanha(D0[2]), fo = sigf(r02);
                        cs0 = ff * cs0 + fi * fg;
                        __half hf = __float2half(fo * tanha(cs0));
                        uf0[c0][16 + un] = hf; uf1[c0][un] = hf;
                    }
                    if (t < ld1) {
                        float fi = sigf(D0[1]), ff = sigf(r01), fg = tanha(D0[3]), fo = sigf(r03);
                        cs1 = ff * cs1 + fi * fg;
                        __half hf = __float2half(fo * tanha(cs1));
                        uf0[c0 + 1][16 + un] = hf; uf1[c0 + 1][un] = hf;
                    }
                } else if (t > 0) {
                    if (t - 1 < ld0) {
                        float fi = sigf(r10), ff = sigf(D1[0]), fg = tanha(r12), fo = sigf(D1[2]);
                        cs0 = ff * cs0 + fi * fg;
                        float h = fo * tanha(cs0);
                        uf1[c0][64 + un] = __float2half(h); h1sh[c0][un] = h;
                    }
                    if (t - 1 < ld1) {
                        float fi = sigf(r11), ff = sigf(D1[1]), fg = tanha(r13), fo = sigf(D1[3]);
                        cs1 = ff * cs1 + fi * fg;
                        float h = fo * tanha(cs1);
                        uf1[c0 + 1][64 + un] = __float2half(h); h1sh[c0 + 1][un] = h;
                    }
                }
            }
        }
        __syncthreads();

        // ---- phase B: deferred projection (row t) + GEMMs ----
        if (tid < 32 && t > 0 && (t - 1) < ldec[ds]) {
            float a0 = bdsh[dk], a1 = 0.f, a2 = 0.f, a3 = 0.f;
            #pragma unroll
            for (int j = 0; j < HID; j += 4) {
                a0 = fmaf(wdsh[dk * 65 + j    ], h1sh[ds][j    ], a0);
                a1 = fmaf(wdsh[dk * 65 + j + 1], h1sh[ds][j + 1], a1);
                a2 = fmaf(wdsh[dk * 65 + j + 2], h1sh[ds][j + 2], a2);
                a3 = fmaf(wdsh[dk * 65 + j + 3], h1sh[ds][j + 3], a3);
            }
            out[((size_t)(s0 + ds) * TCC + t) * FD + dk] = (a0 + a1) + (a2 + a3);
        }
        {
            float p0 = b1a, p1 = b1a, p2 = b1b, p3 = b1b;
            float s0v = 0.f, s1v = 0.f, s2v = 0.f, s3v = 0.f;
            #pragma unroll
            for (int kt = 0; kt < 4; kt++) {
                uint32_t bv0 = *reinterpret_cast<const uint32_t*>(&uf1[g][kt * 16 + c0]);
                uint32_t bv1 = *reinterpret_cast<const uint32_t*>(&uf1[g][kt * 16 + c0 + 8]);
                mma16816(p0, p1, p2, p3, f1[kt][0], f1[kt][1], f1[kt][2], f1[kt][3], bv0, bv1);
            }
            #pragma unroll
            for (int kt = 4; kt < 8; kt++) {
                uint32_t bv0 = *reinterpret_cast<const uint32_t*>(&uf1[g][kt * 16 + c0]);
                uint32_t bv1 = *reinterpret_cast<const uint32_t*>(&uf1[g][kt * 16 + c0 + 8]);
                mma16816(s0v, s1v, s2v, s3v, f1[kt][0], f1[kt][1], f1[kt][2], f1[kt][3], bv0, bv1);
            }
            D1[0] = p0 + s0v; D1[1] = p1 + s1v; D1[2] = p2 + s2v; D1[3] = p3 + s3v;

            float u0 = b0a, u1 = b0a, u2 = b0b, u3 = b0b;
            float v0 = 0.f, v1 = 0.f, v2 = 0.f, v3 = 0.f;
            #pragma unroll
            for (int kt = 0; kt < 3; kt++) {
                uint32_t bv0 = *reinterpret_cast<const uint32_t*>(&uf0[g][kt * 16 + c0]);
                uint32_t bv1 = *reinterpret_cast<const uint32_t*>(&uf0[g][kt * 16 + c0 + 8]);
                mma16816(u0, u1, u2, u3, f0[kt][0], f0[kt][1], f0[kt][2], f0[kt][3], bv0, bv1);
            }
            #pragma unroll
            for (int kt = 3; kt < 5; kt++) {
                uint32_t bv0 = *reinterpret_cast<const uint32_t*>(&uf0[g][kt * 16 + c0]);
                uint32_t bv1 = *reinterpret_cast<const uint32_t*>(&uf0[g][kt * 16 + c0 + 8]);
                mma16816(v0, v1, v2, v3, f0[kt][0], f0[kt][1], f0[kt][2], f0[kt][3], bv0, bv1);
            }
            D0[0] = u0 + v0; D0[1] = u1 + v1; D0[2] = u2 + v2; D0[3] = u3 + v3;
        }
        __syncthreads();
    }

    // ---- decoder epilogue: combine1(Tdec-1), then final projection ----
    {
        float r10 = sx16(D1[0]), r11 = sx16(D1[1]), r12 = sx16(D1[2]), r13 = sx16(D1[3]);
        if (q < 2 && !low) {
            if (Tdec - 1 < ld0) {
                float fi = sigf(r10), ff = sigf(D1[0]), fg = tanha(r12), fo = sigf(D1[2]);
                cs0 = ff * cs0 + fi * fg;
                h1sh[c0][un] = fo * tanha(cs0);
            }
            if (Tdec - 1 < ld1) {
                float fi = sigf(r11), ff = sigf(D1[1]), fg = tanha(r13), fo = sigf(D1[3]);
                cs1 = ff * cs1 + fi * fg;
                h1sh[c0 + 1][un] = fo * tanha(cs1);
            }
        }
    }
    __syncthreads();
    if (tid < 32 && (Tdec - 1) < ldec[ds]) {
        float a0 = bdsh[dk], a1 = 0.f, a2 = 0.f, a3 = 0.f;
        #pragma unroll
        for (int j = 0; j < HID; j += 4) {
            a0 = fmaf(wdsh[dk * 65 + j    ], h1sh[ds][j    ], a0);
            a1 = fmaf(wdsh[dk * 65 + j + 1], h1sh[ds][j + 1], a1);
            a2 = fmaf(wdsh[dk * 65 + j + 2], h1sh[ds][j + 2], a2);
            a3 = fmaf(wdsh[dk * 65 + j + 3], h1sh[ds][j + 3], a3);
        }
        out[((size_t)(s0 + ds) * TCC + Tdec) * FD + dk] = (a0 + a1) + (a2 + a3);
    }
}

extern "C" void kernel_launch(void* const* d_in, const int* in_sizes, int n_in,
                              void* d_out, int out_size) {
    (void)in_sizes; (void)n_in; (void)out_size;
    lstm_ar_kernel<<<BB / SPB, NT>>>(
        (const float*)d_in[0],  (const int*)d_in[1],
        (const float*)d_in[2],  (const int*)d_in[3],
        (const float*)d_in[4],  (const float*)d_in[5],
        (const float*)d_in[6],  (const float*)d_in[7],
        (const float*)d_in[8],  (const float*)d_in[9],
        (const float*)d_in[10], (const float*)d_in[11],
        (const float*)d_in[12], (const float*)d_in[13],
        (float*)d_out);
}

// round 12
// speedup vs baseline: 1.5499x; 1.5499x over previous
#include <cuda_runtime.h>
#include <cuda_fp16.h>
#include <stdint.h>

#define BB   512
#define TW   512
#define TCC  512
#define INP  16
#define HID  64
#define FD   8
#define SPB  4
#define NT   256
#define HPAD 68
#define GPAD 260   // gate array stride (floats): kills q0/q1 STS bank conflict
#define U0S  88    // uf0 stride in halfs (K=80 + pad)
#define U1S  136   // uf1 stride in halfs (K=128 + pad)

__device__ __forceinline__ float tanha(float x) {
    float r; asm("tanh.approx.f32 %0, %1;" : "=f"(r) : "f"(x)); return r;
}
__device__ __forceinline__ float sigf(float x) {
    return fmaf(tanha(0.5f * x), 0.5f, 0.5f);
}
__device__ __forceinline__ uint32_t h2(float a, float b) {
    __half2 h = __floats2half2_rn(a, b);
    return *reinterpret_cast<uint32_t*>(&h);
}
__device__ __forceinline__ void mma16816(
    float* d, const uint32_t* a, uint32_t b0, uint32_t b1)
{
    asm("mma.sync.aligned.m16n8k16.row.col.f32.f16.f16.f32 "
        "{%0,%1,%2,%3},{%4,%5,%6,%7},{%8,%9},{%0,%1,%2,%3};"
        : "+f"(d[0]), "+f"(d[1]), "+f"(d[2]), "+f"(d[3])
        : "r"(a[0]), "r"(a[1]), "r"(a[2]), "r"(a[3]), "r"(b0), "r"(b1));
}

__global__ __launch_bounds__(NT, 1) void lstm_ar_kernel(
    const float* __restrict__ x,     const int* __restrict__ lenx_g,
    const float* __restrict__ ctx,   const int* __restrict__ lctx_g,
    const float* __restrict__ Wih0,  const float* __restrict__ Whh0,
    const float* __restrict__ bih0,  const float* __restrict__ bhh0,
    const float* __restrict__ Wih1,  const float* __restrict__ Whh1,
    const float* __restrict__ bih1,  const float* __restrict__ bhh1,
    const float* __restrict__ Wd,    const float* __restrict__ bd,
    float* __restrict__ out)
{
    __shared__ __align__(16) __half uf0[8][U0S];   // [x(16)|h0(64)] per sample, K=80
    __shared__ __align__(16) __half uf1[8][U1S];   // [h0|h1] per sample, K=128
    __shared__ __align__(16) float g0sh[SPB][GPAD];
    __shared__ __align__(16) float g1sh[SPB][GPAD];
    __shared__ __align__(16) float h1sh[SPB][HPAD];
    __shared__ float wdsh[FD * 65];
    __shared__ float bdsh[FD];
    __shared__ float elem[SPB][FD];
    __shared__ int   lens[SPB];
    __shared__ int   ldec[SPB];

    const int tid = threadIdx.x;
    const int s0  = blockIdx.x * SPB;

    // ---- fill invalid output rows with -999 ----
    {
        const float4 m = make_float4(-999.f, -999.f, -999.f, -999.f);
        #pragma unroll
        for (int s = 0; s < SPB; s++) {
            int lc = lctx_g[s0 + s];
            float4* po = (float4*)(out + (size_t)(s0 + s) * TCC * FD);
            for (int i = lc * 2 + tid; i < (TCC * FD) / 4; i += NT) po[i] = m;
        }
    }

    // ---- zero B buffers (samples 4..7 stay zero) ----
    {
        __half z = __float2half(0.f);
        __half* p0 = &uf0[0][0];
        for (int i = tid; i < 8 * U0S; i += NT) p0[i] = z;
        __half* p1 = &uf1[0][0];
        for (int i = tid; i < 8 * U1S; i += NT) p1[i] = z;
    }

    // ---- mma identities: warp w owns M-tiles 2w, 2w+1 (rows 32w..32w+31) ----
    const int w    = tid >> 5, lane = tid & 31;
    const int g    = lane >> 2, q = lane & 3;
    const int c0   = 2 * q;
    int rAj[2], rBj[2];
    rAj[0] = 32 * w + g;       rBj[0] = rAj[0] + 8;
    rAj[1] = 32 * w + 16 + g;  rBj[1] = rAj[1] + 8;

    // A fragments (fp16 weights): f0 = [Wih0|Whh0] K=80, f1 = [Wih1|Whh1] K=128
    uint32_t f0[2][5][4], f1[2][8][4];
    float b0A[2], b0B[2], b1A[2], b1B[2];
    #pragma unroll
    for (int j = 0; j < 2; j++) {
        int rA = rAj[j], rB = rBj[j];
        f0[j][0][0] = h2(Wih0[rA * INP + c0],     Wih0[rA * INP + c0 + 1]);
        f0[j][0][1] = h2(Wih0[rB * INP + c0],     Wih0[rB * INP + c0 + 1]);
        f0[j][0][2] = h2(Wih0[rA * INP + c0 + 8], Wih0[rA * INP + c0 + 9]);
        f0[j][0][3] = h2(Wih0[rB * INP + c0 + 8], Wih0[rB * INP + c0 + 9]);
        #pragma unroll
        for (int kt = 1; kt < 5; kt++) {
            int kb = (kt - 1) * 16;
            f0[j][kt][0] = h2(Whh0[rA * HID + kb + c0],     Whh0[rA * HID + kb + c0 + 1]);
            f0[j][kt][1] = h2(Whh0[rB * HID + kb + c0],     Whh0[rB * HID + kb + c0 + 1]);
            f0[j][kt][2] = h2(Whh0[rA * HID + kb + c0 + 8], Whh0[rA * HID + kb + c0 + 9]);
            f0[j][kt][3] = h2(Whh0[rB * HID + kb + c0 + 8], Whh0[rB * HID + kb + c0 + 9]);
        }
        #pragma unroll
        for (int kt = 0; kt < 4; kt++) {
            int kb = kt * 16;
            f1[j][kt][0] = h2(Wih1[rA * HID + kb + c0],     Wih1[rA * HID + kb + c0 + 1]);
            f1[j][kt][1] = h2(Wih1[rB * HID + kb + c0],     Wih1[rB * HID + kb + c0 + 1]);
            f1[j][kt][2] = h2(Wih1[rA * HID + kb + c0 + 8], Wih1[rA * HID + kb + c0 + 9]);
            f1[j][kt][3] = h2(Wih1[rB * HID + kb + c0 + 8], Wih1[rB * HID + kb + c0 + 9]);
        }
        #pragma unroll
        for (int kt = 4; kt < 8; kt++) {
            int kb = (kt - 4) * 16;
            f1[j][kt][0] = h2(Whh1[rA * HID + kb + c0],     Whh1[rA * HID + kb + c0 + 1]);
            f1[j][kt][1] = h2(Whh1[rB * HID + kb + c0],     Whh1[rB * HID + kb + c0 + 1]);
            f1[j][kt][2] = h2(Whh1[rA * HID + kb + c0 + 8], Whh1[rA * HID + kb + c0 + 9]);
            f1[j][kt][3] = h2(Whh1[rB * HID + kb + c0 + 8], Whh1[rB * HID + kb + c0 + 9]);
        }
        b0A[j] = bih0[rA] + bhh0[rA]; b0B[j] = bih0[rB] + bhh0[rB];
        b1A[j] = bih1[rA] + bhh1[rA]; b1B[j] = bih1[rB] + bhh1[rB];
    }

    if (tid < SPB) { lens[tid] = lenx_g[s0 + tid]; ldec[tid] = lctx_g[s0 + tid] - 1; }
    for (int i = tid; i < FD * HID; i += NT) wdsh[(i >> 6) * 65 + (i & 63)] = Wd[i];
    if (tid < FD) bdsh[tid] = bd[tid];
    h1sh[tid >> 6][tid & 63] = 0.f;

    __syncthreads();

    const int Tenc = max(max(lens[0], lens[1]), max(lens[2], lens[3]));
    const int Tdec = max(max(ldec[0], ldec[1]), max(ldec[2], ldec[3]));

    // ---- combine ownership: lay = layer, each thread covers samples spp, spp+2 ----
    const int lay = tid >> 7;
    const int rem = tid & 127;
    const int spp = rem >> 6, cj = rem & 63;
    const int smA = spp, smB = spp + 2;
    const int eLa = lens[smA], eLb = lens[smB];
    const int dLa = ldec[smA], dLb = ldec[smB];
    float cA = 0.f, cB = 0.f;   // cell states (layer `lay`) for samples smA, smB

    const int ps = tid >> 4, pk = tid & 15;  // x prefetch (tid < 64)
    const int ds = tid >> 3, dk = tid & 7;   // ctx prefetch / projection (tid < 32)

    // ---- encoder prologue: x(0) -> uf0; g0(0) (h0 = 0) ----
    if (tid < 64) uf0[ps][pk] = __float2half(x[((size_t)(s0 + ps) * TW) * INP + pk]);
    __syncthreads();
    {
        float d0[4] = {b0A[0], b0A[0], b0B[0], b0B[0]};
        float d1[4] = {b0A[1], b0A[1], b0B[1], b0B[1]};
        #pragma unroll
        for (int kt = 0; kt < 5; kt++) {
            uint32_t bv0 = *reinterpret_cast<const uint32_t*>(&uf0[g][kt * 16 + c0]);
            uint32_t bv1 = *reinterpret_cast<const uint32_t*>(&uf0[g][kt * 16 + c0 + 8]);
            mma16816(d0, f0[0][kt], bv0, bv1);
            mma16816(d1, f0[1][kt], bv0, bv1);
        }
        if (q < 2) {
            int sA = 2 * q, sB = 2 * q + 1;
            g0sh[sA][rAj[0]] = d0[0]; g0sh[sB][rAj[0]] = d0[1];
            g0sh[sA][rBj[0]] = d0[2]; g0sh[sB][rBj[0]] = d0[3];
            g0sh[sA][rAj[1]] = d1[0]; g0sh[sB][rAj[1]] = d1[1];
            g0sh[sA][rBj[1]] = d1[2]; g0sh[sB][rBj[1]] = d1[3];
        }
    }
    float xn = 0.f;
    if (tid < 64) xn = x[((size_t)(s0 + ps) * TW + min(1, TW - 1)) * INP + pk];
    __syncthreads();

    // ===================== encoder =====================
    for (int t = 0; t < Tenc; t++) {
        // ---- phase A: combine + h STS + x rotate ----
        if (tid < 64) {
            uf0[ps][pk] = __float2half(xn);
            int tt = (t + 2 < TW) ? t + 2 : TW - 1;
            xn = x[((size_t)(s0 + ps) * TW + tt) * INP + pk];
        }
        if (lay == 0) {
            if (t < eLa) {
                float fi = sigf(g0sh[smA][cj]),       ff = sigf(g0sh[smA][64 + cj]);
                float fg = tanha(g0sh[smA][128 + cj]), fo = sigf(g0sh[smA][192 + cj]);
                cA = ff * cA + fi * fg;
                __half hf = __float2half(fo * tanha(cA));
                uf0[smA][16 + cj] = hf; uf1[smA][cj] = hf;
            }
            if (t < eLb) {
                float fi = sigf(g0sh[smB][cj]),       ff = sigf(g0sh[smB][64 + cj]);
                float fg = tanha(g0sh[smB][128 + cj]), fo = sigf(g0sh[smB][192 + cj]);
                cB = ff * cB + fi * fg;
                __half hf = __float2half(fo * tanha(cB));
                uf0[smB][16 + cj] = hf; uf1[smB][cj] = hf;
            }
        } else if (t > 0) {
            if (t - 1 < eLa) {
                float fi = sigf(g1sh[smA][cj]),       ff = sigf(g1sh[smA][64 + cj]);
                float fg = tanha(g1sh[smA][128 + cj]), fo = sigf(g1sh[smA][192 + cj]);
                cA = ff * cA + fi * fg;
                float h = fo * tanha(cA);
                uf1[smA][64 + cj] = __float2half(h); h1sh[smA][cj] = h;
            }
            if (t - 1 < eLb) {
                float fi = sigf(g1sh[smB][cj]),       ff = sigf(g1sh[smB][64 + cj]);
                float fg = tanha(g1sh[smB][128 + cj]), fo = sigf(g1sh[smB][192 + cj]);
                cB = ff * cB + fi * fg;
                float h = fo * tanha(cB);
                uf1[smB][64 + cj] = __float2half(h); h1sh[smB][cj] = h;
            }
        }
        __syncthreads();

        // ---- phase B: g1(t) and g0(t+1), B fragments shared across 2 tiles ----
        {
            float e0[4] = {b1A[0], b1A[0], b1B[0], b1B[0]};
            float e1[4] = {b1A[1], b1A[1], b1B[1], b1B[1]};
            #pragma unroll
            for (int kt = 0; kt < 8; kt++) {
                uint32_t bv0 = *reinterpret_cast<const uint32_t*>(&uf1[g][kt * 16 + c0]);
                uint32_t bv1 = *reinterpret_cast<const uint32_t*>(&uf1[g][kt * 16 + c0 + 8]);
                mma16816(e0, f1[0][kt], bv0, bv1);
                mma16816(e1, f1[1][kt], bv0, bv1);
            }
            float d0[4] = {b0A[0], b0A[0], b0B[0], b0B[0]};
            float d1[4] = {b0A[1], b0A[1], b0B[1], b0B[1]};
            #pragma unroll
            for (int kt = 0; kt < 5; kt++) {
                uint32_t bv0 = *reinterpret_cast<const uint32_t*>(&uf0[g][kt * 16 + c0]);
                uint32_t bv1 = *reinterpret_cast<const uint32_t*>(&uf0[g][kt * 16 + c0 + 8]);
                mma16816(d0, f0[0][kt], bv0, bv1);
                mma16816(d1, f0[1][kt], bv0, bv1);
            }
            if (q < 2) {
                int sA = 2 * q, sB = 2 * q + 1;
                g1sh[sA][rAj[0]] = e0[0]; g1sh[sB][rAj[0]] = e0[1];
                g1sh[sA][rBj[0]] = e0[2]; g1sh[sB][rBj[0]] = e0[3];
                g1sh[sA][rAj[1]] = e1[0]; g1sh[sB][rAj[1]] = e1[1];
                g1sh[sA][rBj[1]] = e1[2]; g1sh[sB][rBj[1]] = e1[3];
                g0sh[sA][rAj[0]] = d0[0]; g0sh[sB][rAj[0]] = d0[1];
                g0sh[sA][rBj[0]] = d0[2]; g0sh[sB][rBj[0]] = d0[3];
                g0sh[sA][rAj[1]] = d1[0]; g0sh[sB][rAj[1]] = d1[1];
                g0sh[sA][rBj[1]] = d1[2]; g0sh[sB][rBj[1]] = d1[3];
            }
        }
        __syncthreads();
    }

    // ---- encoder epilogue: combine1(Tenc-1) ----
    if (lay == 1) {
        if (Tenc - 1 < eLa) {
            float fi = sigf(g1sh[smA][cj]),       ff = sigf(g1sh[smA][64 + cj]);
            float fg = tanha(g1sh[smA][128 + cj]), fo = sigf(g1sh[smA][192 + cj]);
            cA = ff * cA + fi * fg;
            float h = fo * tanha(cA);
            uf1[smA][64 + cj] = __float2half(h); h1sh[smA][cj] = h;
        }
        if (Tenc - 1 < eLb) {
            float fi = sigf(g1sh[smB][cj]),       ff = sigf(g1sh[smB][64 + cj]);
            float fg = tanha(g1sh[smB][128 + cj]), fo = sigf(g1sh[smB][192 + cj]);
            cB = ff * cB + fi * fg;
            float h = fo * tanha(cB);
            uf1[smB][64 + cj] = __float2half(h); h1sh[smB][cj] = h;
        }
    }
    __syncthreads();

    // ===================== element = h1 @ Wd.T + bd =====================
    if (tid < 32) {
        float a0 = bdsh[dk], a1 = 0.f, a2 = 0.f, a3 = 0.f;
        #pragma unroll
        for (int j = 0; j < HID; j += 4) {
            a0 = fmaf(wdsh[dk * 65 + j    ], h1sh[ds][j    ], a0);
            a1 = fmaf(wdsh[dk * 65 + j + 1], h1sh[ds][j + 1], a1);
            a2 = fmaf(wdsh[dk * 65 + j + 2], h1sh[ds][j + 2], a2);
            a3 = fmaf(wdsh[dk * 65 + j + 3], h1sh[ds][j + 3], a3);
        }
        float e = (a0 + a1) + (a2 + a3);
        elem[ds][dk] = e;
        out[(size_t)(s0 + ds) * TCC * FD + dk] = e;
    }
    __syncthreads();

    // ---- decoder prologue: dec input = [elem | ctx(0)]; g0_dec(0) ----
    if (tid < 64 && pk < 8) uf0[ps][pk] = __float2half(elem[ps][pk]);
    if (tid < 32) uf0[ds][8 + dk] = __float2half(ctx[((size_t)(s0 + ds) * TCC) * FD + dk]);
    __syncthreads();
    {
        float d0[4] = {b0A[0], b0A[0], b0B[0], b0B[0]};
        float d1[4] = {b0A[1], b0A[1], b0B[1], b0B[1]};
        #pragma unroll
        for (int kt = 0; kt < 5; kt++) {
            uint32_t bv0 = *reinterpret_cast<const uint32_t*>(&uf0[g][kt * 16 + c0]);
            uint32_t bv1 = *reinterpret_cast<const uint32_t*>(&uf0[g][kt * 16 + c0 + 8]);
            mma16816(d0, f0[0][kt], bv0, bv1);
            mma16816(d1, f0[1][kt], bv0, bv1);
        }
        if (q < 2) {
            int sA = 2 * q, sB = 2 * q + 1;
            g0sh[sA][rAj[0]] = d0[0]; g0sh[sB][rAj[0]] = d0[1];
            g0sh[sA][rBj[0]] = d0[2]; g0sh[sB][rBj[0]] = d0[3];
            g0sh[sA][rAj[1]] = d1[0]; g0sh[sB][rAj[1]] = d1[1];
            g0sh[sA][rBj[1]] = d1[2]; g0sh[sB][rBj[1]] = d1[3];
        }
    }
    float cn = 0.f;
    if (tid < 32) cn = ctx[((size_t)(s0 + ds) * TCC + min(1, TCC - 1)) * FD + dk];
    __syncthreads();

    // ===================== decoder =====================
    for (int t = 0; t < Tdec; t++) {
        // ---- phase A: combine + ctx rotate ----
        if (tid < 32) {
            uf0[ds][8 + dk] = __float2half(cn);
            int tt = (t + 2 < TCC) ? t + 2 : TCC - 1;
            cn = ctx[((size_t)(s0 + ds) * TCC + tt) * FD + dk];
        }
        if (lay == 0) {
            if (t < dLa) {
                float fi = sigf(g0sh[smA][cj]),       ff = sigf(g0sh[smA][64 + cj]);
                float fg = tanha(g0sh[smA][128 + cj]), fo = sigf(g0sh[smA][192 + cj]);
                cA = ff * cA + fi * fg;
                __half hf = __float2half(fo * tanha(cA));
                uf0[smA][16 + cj] = hf; uf1[smA][cj] = hf;
            }
            if (t < dLb) {
                float fi = sigf(g0sh[smB][cj]),       ff = sigf(g0sh[smB][64 + cj]);
                float fg = tanha(g0sh[smB][128 + cj]), fo = sigf(g0sh[smB][192 + cj]);
                cB = ff * cB + fi * fg;
                __half hf = __float2half(fo * tanha(cB));
                uf0[smB][16 + cj] = hf; uf1[smB][cj] = hf;
            }
        } else if (t > 0) {
            if (t - 1 < dLa) {
                float fi = sigf(g1sh[smA][cj]),       ff = sigf(g1sh[smA][64 + cj]);
                float fg = tanha(g1sh[smA][128 + cj]), fo = sigf(g1sh[smA][192 + cj]);
                cA = ff * cA + fi * fg;
                float h = fo * tanha(cA);
                uf1[smA][64 + cj] = __float2half(h); h1sh[smA][cj] = h;
            }
            if (t - 1 < dLb) {
                float fi = sigf(g1sh[smB][cj]),       ff = sigf(g1sh[smB][64 + cj]);
                float fg = tanha(g1sh[smB][128 + cj]), fo = sigf(g1sh[smB][192 + cj]);
                cB = ff * cB + fi * fg;
                float h = fo * tanha(cB);
                uf1[smB][64 + cj] = __float2half(h); h1sh[smB][cj] = h;
            }
        }
        __syncthreads();

        // ---- phase B: deferred projection + GEMMs ----
        if (tid < 32 && t > 0 && (t - 1) < ldec[ds]) {
            float a0 = bdsh[dk], a1 = 0.f, a2 = 0.f, a3 = 0.f;
            #pragma unroll
            for (int j = 0; j < HID; j += 4) {
                a0 = fmaf(wdsh[dk * 65 + j    ], h1sh[ds][j    ], a0);
                a1 = fmaf(wdsh[dk * 65 + j + 1], h1sh[ds][j + 1], a1);
                a2 = fmaf(wdsh[dk * 65 + j + 2], h1sh[ds][j + 2], a2);
                a3 = fmaf(wdsh[dk * 65 + j + 3], h1sh[ds][j + 3], a3);
            }
            out[((size_t)(s0 + ds) * TCC + t) * FD + dk] = (a0 + a1) + (a2 + a3);
        }
        {
            float e0[4] = {b1A[0], b1A[0], b1B[0], b1B[0]};
            float e1[4] = {b1A[1], b1A[1], b1B[1], b1B[1]};
            #pragma unroll
            for (int kt = 0; kt < 8; kt++) {
                uint32_t bv0 = *reinterpret_cast<const uint32_t*>(&uf1[g][kt * 16 + c0]);
                uint32_t bv1 = *reinterpret_cast<const uint32_t*>(&uf1[g][kt * 16 + c0 + 8]);
                mma16816(e0, f1[0][kt], bv0, bv1);
                mma16816(e1, f1[1][kt], bv0, bv1);
            }
            float d0[4] = {b0A[0], b0A[0], b0B[0], b0B[0]};
            float d1[4] = {b0A[1], b0A[1], b0B[1], b0B[1]};
            #pragma unroll
            for (int kt = 0; kt < 5; kt++) {
                uint32_t bv0 = *reinterpret_cast<const uint32_t*>(&uf0[g][kt * 16 + c0]);
                uint32_t bv1 = *reinterpret_cast<const uint32_t*>(&uf0[g][kt * 16 + c0 + 8]);
                mma16816(d0, f0[0][kt], bv0, bv1);
                mma16816(d1, f0[1][kt], bv0, bv1);
            }
            if (q < 2) {
                int sA = 2 * q, sB = 2 * q + 1;
                g1sh[sA][rAj[0]] = e0[0]; g1sh[sB][rAj[0]] = e0[1];
                g1sh[sA][rBj[0]] = e0[2]; g1sh[sB][rBj[0]] = e0[3];
                g1sh[sA][rAj[1]] = e1[0]; g1sh[sB][rAj[1]] = e1[1];
                g1sh[sA][rBj[1]] = e1[2]; g1sh[sB][rBj[1]] = e1[3];
                g0sh[sA][rAj[0]] = d0[0]; g0sh[sB][rAj[0]] = d0[1];
                g0sh[sA][rBj[0]] = d0[2]; g0sh[sB][rBj[0]] = d0[3];
                g0sh[sA][rAj[1]] = d1[0]; g0sh[sB][rAj[1]] = d1[1];
                g0sh[sA][rBj[1]] = d1[2]; g0sh[sB][rBj[1]] = d1[3];
            }
        }
        __syncthreads();
    }

    // ---- decoder epilogue: combine1(Tdec-1), then final projection ----
    if (lay == 1) {
        if (Tdec - 1 < dLa) {
            float fi = sigf(g1sh[smA][cj]),       ff = sigf(g1sh[smA][64 + cj]);
            float fg = tanha(g1sh[smA][128 + cj]), fo = sigf(g1sh[smA][192 + cj]);
            cA = ff * cA + fi * fg;
            h1sh[smA][cj] = fo * tanha(cA);
        }
        if (Tdec - 1 < dLb) {
            float fi = sigf(g1sh[smB][cj]),       ff = sigf(g1sh[smB][64 + cj]);
            float fg = tanha(g1sh[smB][128 + cj]), fo = sigf(g1sh[smB][192 + cj]);
            cB = ff * cB + fi * fg;
            h1sh[smB][cj] = fo * tanha(cB);
        }
    }
    __syncthreads();
    if (tid < 32 && (Tdec - 1) < ldec[ds]) {
        float a0 = bdsh[dk], a1 = 0.f, a2 = 0.f, a3 = 0.f;
        #pragma unroll
        for (int j = 0; j < HID; j += 4) {
            a0 = fmaf(wdsh[dk * 65 + j    ], h1sh[ds][j    ], a0);
            a1 = fmaf(wdsh[dk * 65 + j + 1], h1sh[ds][j + 1], a1);
            a2 = fmaf(wdsh[dk * 65 + j + 2], h1sh[ds][j + 2], a2);
            a3 = fmaf(wdsh[dk * 65 + j + 3], h1sh[ds][j + 3], a3);
        }
        out[((size_t)(s0 + ds) * TCC + Tdec) * FD + dk] = (a0 + a1) + (a2 + a3);
    }
}

extern "C" void kernel_launch(void* const* d_in, const int* in_sizes, int n_in,
                              void* d_out, int out_size) {
    (void)in_sizes; (void)n_in; (void)out_size;
    lstm_ar_kernel<<<BB / SPB, NT>>>(
        (const float*)d_in[0],  (const int*)d_in[1],
        (const float*)d_in[2],  (const int*)d_in[3],
        (const float*)d_in[4],  (const float*)d_in[5],
        (const float*)d_in[6],  (const float*)d_in[7],
        (const float*)d_in[8],  (const float*)d_in[9],
        (const float*)d_in[10], (const float*)d_in[11],
        (const float*)d_in[12], (const float*)d_in[13],
        (float*)d_out);
}